// round 15
// baseline (speedup 1.0000x reference)
#include <cuda_runtime.h>

// MoE conditional FFN: T=16, TOP_K=2, E=8, H=1024, I=2816, fp32.
//
// R10: phase2 rebuilt around LOAD BALANCE:
//  - work unit = (chunk of <=4 token-expert pairs) x (32 up-rows)
//  - chunk list computed deterministically per block from eidx (32 ints)
//  - grid (32, 16): every active block does IDENTICAL work, single wave
//  - inline weight loads (no explicit float4 buffers -> no forced liveness,
//    ptxas picks pipeline depth; R8/R9's explicit buffers spilled at 128 regs)
//  - 4-pair interleaved accumulators vs smem-staged h (fast consume + ILP)
//  - __launch_bounds__(256,3): <=84 regs, 24 warps/SM, 3x45.5KB smem fits.
// Phase1 (6.45 TB/s measured) untouched.

#define NTOK   16
#define TOPK   2
#define NPAIR  (NTOK * TOPK)       // 32
#define HID    1024
#define INTER  2816
#define NEXP   8
#define I4     (INTER / 4)         // 704 float4 per row
#define MAXCH  16                  // >= max possible chunks (14)

__device__ float g_h[NPAIR * INTER];   // 360 KB scratch

__device__ __forceinline__ float dot4(float4 a, float4 b, float acc) {
    acc = fmaf(a.x, b.x, acc);
    acc = fmaf(a.y, b.y, acc);
    acc = fmaf(a.z, b.z, acc);
    return fmaf(a.w, b.w, acc);
}

// ---------------------------------------------------------------------------
// Phase 1 (R1's proven version): gate & down GEMVs + SiLU-mul. Untouched.
// ---------------------------------------------------------------------------
__global__ __launch_bounds__(256, 2)
void moe_phase1(const float* __restrict__ x,        // [T, H]
                const int*   __restrict__ eidx,     // [T, TOPK]
                const float* __restrict__ gate,     // [E, I, H]
                const float* __restrict__ down)     // [E, I, H]
{
    const int e = blockIdx.y;

    __shared__ int s_cnt;
    __shared__ int s_pair[NPAIR];
    if (threadIdx.x == 0) {
        int c = 0;
        #pragma unroll
        for (int i = 0; i < NPAIR; i++)
            if (eidx[i] == e) s_pair[c++] = i;
        s_cnt = c;
    }
    __syncthreads();
    const int cnt = s_cnt;
    if (cnt == 0) return;

    const int warp = threadIdx.x >> 5;
    const int lane = threadIdx.x & 31;
    const int row0 = blockIdx.x * 32 + warp * 4;

    const float4* gate4 = reinterpret_cast<const float4*>(gate + (size_t)e * INTER * HID);
    const float4* down4 = reinterpret_cast<const float4*>(down + (size_t)e * INTER * HID);

    for (int rr = 0; rr < 4; rr++) {
        const int row = row0 + rr;
        const float4* gr = gate4 + (size_t)row * (HID / 4);
        const float4* dr = down4 + (size_t)row * (HID / 4);

        float4 g4[8], d4[8];
        #pragma unroll
        for (int j = 0; j < 8; j++) {
            g4[j] = gr[lane + 32 * j];
            d4[j] = dr[lane + 32 * j];
        }

        for (int p = 0; p < cnt; p++) {
            const int pa = s_pair[p];
            const int t  = pa >> 1;
            const float4* xr = reinterpret_cast<const float4*>(x + (size_t)t * HID);

            float ag = 0.f, ad = 0.f;
            #pragma unroll
            for (int j = 0; j < 8; j++) {
                const float4 x4 = xr[lane + 32 * j];
                ag = dot4(g4[j], x4, ag);
                ad = dot4(d4[j], x4, ad);
            }
            #pragma unroll
            for (int off = 16; off; off >>= 1) {
                ag += __shfl_xor_sync(0xFFFFFFFFu, ag, off);
                ad += __shfl_xor_sync(0xFFFFFFFFu, ad, off);
            }
            if (lane == 0) {
                const float s = ag / (1.f + __expf(-ag));   // silu(gate)
                g_h[(size_t)pa * INTER + row] = s * ad;
            }
        }
    }
}

// ---------------------------------------------------------------------------
// Phase 2: out[pair,hh] = up[e,hh,:] . h[pair,:]
// grid = (HID/32, MAXCH), block = 256 (8 warps).
// blockIdx.y selects ONE <=4-pair chunk of one expert (list rebuilt locally);
// block stages that chunk's 4 h-rows (padded with chunk's first pair) into
// smem, then each warp computes 4 up-rows with 4 interleaved acc chains.
// ---------------------------------------------------------------------------
__global__ __launch_bounds__(256, 3)
void moe_phase2(const int*   __restrict__ eidx,     // [T, TOPK]
                const float* __restrict__ up,       // [E, H, I]
                float*       __restrict__ out)      // [T, TOPK, H]
{
    __shared__ float s_h[4 * INTER];                // 45056 B
    __shared__ int s_e;                             // expert of this chunk
    __shared__ int s_cp[4];                         // this chunk's pairs (padded)
    __shared__ int s_valid;

    const int tid = threadIdx.x;

    // Deterministic chunk enumeration (same in every block); pick chunk
    // number blockIdx.y. Cheap: scans 32 ints, thread 0 only.
    if (tid == 0) {
        const int target = blockIdx.y;
        int nch = 0, found = 0;
        for (int e = 0; e < NEXP && !found; e++) {
            int cp[NPAIR];
            int c = 0;
            #pragma unroll
            for (int i = 0; i < NPAIR; i++)
                if (eidx[i] == e) cp[c++] = i;
            for (int b = 0; b < c; b += 4) {
                if (nch == target) {
                    const int n = (c - b < 4) ? (c - b) : 4;
                    #pragma unroll
                    for (int k = 0; k < 4; k++)
                        s_cp[k] = cp[b + (k < n ? k : 0)];   // pad w/ first
                    s_e = e;
                    found = 1;
                    break;
                }
                nch++;
            }
        }
        s_valid = found;
    }
    __syncthreads();
    if (!s_valid) return;

    const int e = s_e;
    const int pa0 = s_cp[0], pa1 = s_cp[1], pa2 = s_cp[2], pa3 = s_cp[3];

    // Stage 4 h-rows into smem (coalesced 256-thread copy from L2).
    float4* s_h4 = reinterpret_cast<float4*>(s_h);
    for (int i = tid; i < 4 * I4; i += 256) {
        const int pr = i / I4;
        const int k  = i - pr * I4;
        s_h4[i] = reinterpret_cast<const float4*>(
            g_h + (size_t)s_cp[pr] * INTER)[k];
    }
    __syncthreads();

    const int warp = tid >> 5;
    const int lane = tid & 31;
    const int row0 = blockIdx.x * 32 + warp * 4;

    const float4* up4 = reinterpret_cast<const float4*>(up + (size_t)e * HID * INTER);

    for (int rr = 0; rr < 4; rr++) {
        const int row = row0 + rr;
        const float4* ur = up4 + (size_t)row * I4;

        float a0 = 0.f, a1 = 0.f, a2 = 0.f, a3 = 0.f;

        // Inline weight loads: ptxas chooses batching depth within the
        // launch-bounds budget (no forced 64-reg buffer liveness).
        #pragma unroll
        for (int j = 0; j < 22; j++) {
            const int k = lane + 32 * j;
            const float4 u = ur[k];
            a0 = dot4(u, s_h4[k],            a0);
            a1 = dot4(u, s_h4[I4 + k],       a1);
            a2 = dot4(u, s_h4[2 * I4 + k],   a2);
            a3 = dot4(u, s_h4[3 * I4 + k],   a3);
        }

        #pragma unroll
        for (int off = 16; off; off >>= 1) {        // 4 interleaved butterflies
            a0 += __shfl_xor_sync(0xFFFFFFFFu, a0, off);
            a1 += __shfl_xor_sync(0xFFFFFFFFu, a1, off);
            a2 += __shfl_xor_sync(0xFFFFFFFFu, a2, off);
            a3 += __shfl_xor_sync(0xFFFFFFFFu, a3, off);
        }
        if (lane == 0) {
            out[(size_t)pa0 * HID + row] = a0;      // pads rewrite same value
            out[(size_t)pa1 * HID + row] = a1;
            out[(size_t)pa2 * HID + row] = a2;
            out[(size_t)pa3 * HID + row] = a3;
        }
    }
}

// ---------------------------------------------------------------------------
extern "C" void kernel_launch(void* const* d_in, const int* in_sizes, int n_in,
                              void* d_out, int out_size)
{
    const float* x    = (const float*)d_in[0];
    const int*   eidx = (const int*)  d_in[1];
    const float* gate = (const float*)d_in[2];
    const float* up   = (const float*)d_in[3];
    const float* down = (const float*)d_in[4];
    float* out = (float*)d_out;

    dim3 g1(INTER / 32, NEXP);   // 88 x 8
    moe_phase1<<<g1, 256>>>(x, eidx, gate, down);

    dim3 g2(HID / 32, MAXCH);    // 32 x 16 work slots, uniform blocks
    moe_phase2<<<g2, 256>>>(eidx, up, out);
}

// round 16
// speedup vs baseline: 2.0139x; 2.0139x over previous
#include <cuda_runtime.h>

// MoE conditional FFN: T=16, TOP_K=2, E=8, H=1024, I=2816, fp32.
//
// R11 = R7's traffic structure x R10's inner loop:
//  - grid (HID/32, NEXP) = 256 blocks, single wave; weights read ONCE/expert
//    (R10 proved the inner loop streams at 5.3 TB/s but wasted 7x traffic;
//     R7 had minimal traffic but a serial pair loop capped at 2.75 TB/s)
//  - block stages up to 8 h-rows per super-chunk into 90KB dynamic smem
//    (one barrier pair per super-chunk; typical cnt<=8 -> exactly one)
//  - warp = 4 rows; per row, groups of 4 pairs with inline weight loads and
//    4 interleaved acc chains (R10's 80-reg no-spill codegen); group 2's
//    weight re-read is an immediate L1 hit.
// Phase1 (6.45 TB/s measured, ~28.5us) untouched.

#define NTOK   16
#define TOPK   2
#define NPAIR  (NTOK * TOPK)       // 32
#define HID    1024
#define INTER  2816
#define NEXP   8
#define I4     (INTER / 4)         // 704 float4 per row
#define CH     8                   // h-rows per smem super-chunk (90112 B)

__device__ float g_h[NPAIR * INTER];   // 360 KB scratch

__device__ __forceinline__ float dot4(float4 a, float4 b, float acc) {
    acc = fmaf(a.x, b.x, acc);
    acc = fmaf(a.y, b.y, acc);
    acc = fmaf(a.z, b.z, acc);
    return fmaf(a.w, b.w, acc);
}

// ---------------------------------------------------------------------------
// Phase 1 (R1's proven version): gate & down GEMVs + SiLU-mul. Untouched.
// ---------------------------------------------------------------------------
__global__ __launch_bounds__(256, 2)
void moe_phase1(const float* __restrict__ x,        // [T, H]
                const int*   __restrict__ eidx,     // [T, TOPK]
                const float* __restrict__ gate,     // [E, I, H]
                const float* __restrict__ down)     // [E, I, H]
{
    const int e = blockIdx.y;

    __shared__ int s_cnt;
    __shared__ int s_pair[NPAIR];
    if (threadIdx.x == 0) {
        int c = 0;
        #pragma unroll
        for (int i = 0; i < NPAIR; i++)
            if (eidx[i] == e) s_pair[c++] = i;
        s_cnt = c;
    }
    __syncthreads();
    const int cnt = s_cnt;
    if (cnt == 0) return;

    const int warp = threadIdx.x >> 5;
    const int lane = threadIdx.x & 31;
    const int row0 = blockIdx.x * 32 + warp * 4;

    const float4* gate4 = reinterpret_cast<const float4*>(gate + (size_t)e * INTER * HID);
    const float4* down4 = reinterpret_cast<const float4*>(down + (size_t)e * INTER * HID);

    for (int rr = 0; rr < 4; rr++) {
        const int row = row0 + rr;
        const float4* gr = gate4 + (size_t)row * (HID / 4);
        const float4* dr = down4 + (size_t)row * (HID / 4);

        float4 g4[8], d4[8];
        #pragma unroll
        for (int j = 0; j < 8; j++) {
            g4[j] = gr[lane + 32 * j];
            d4[j] = dr[lane + 32 * j];
        }

        for (int p = 0; p < cnt; p++) {
            const int pa = s_pair[p];
            const int t  = pa >> 1;
            const float4* xr = reinterpret_cast<const float4*>(x + (size_t)t * HID);

            float ag = 0.f, ad = 0.f;
            #pragma unroll
            for (int j = 0; j < 8; j++) {
                const float4 x4 = xr[lane + 32 * j];
                ag = dot4(g4[j], x4, ag);
                ad = dot4(d4[j], x4, ad);
            }
            #pragma unroll
            for (int off = 16; off; off >>= 1) {
                ag += __shfl_xor_sync(0xFFFFFFFFu, ag, off);
                ad += __shfl_xor_sync(0xFFFFFFFFu, ad, off);
            }
            if (lane == 0) {
                const float s = ag / (1.f + __expf(-ag));   // silu(gate)
                g_h[(size_t)pa * INTER + row] = s * ad;
            }
        }
    }
}

// ---------------------------------------------------------------------------
// Phase 2: out[pair,hh] = up[e,hh,:] . h[pair,:]
// grid = (HID/32, NEXP) = 256 blocks (single wave), block = 256 (8 warps).
// Super-chunks of up to 8 pairs staged once into 90KB dynamic smem; warp does
// 4 rows; per row, groups of 4 pairs with R10's inline-load interleaved loop.
// ---------------------------------------------------------------------------
__global__ __launch_bounds__(256, 2)
void moe_phase2(const int*   __restrict__ eidx,     // [T, TOPK]
                const float* __restrict__ up,       // [E, H, I]
                float*       __restrict__ out)      // [T, TOPK, H]
{
    extern __shared__ float s_h[];                  // CH * INTER floats
    __shared__ int s_cnt4;
    __shared__ int s_pair[NPAIR + 3];

    const int e   = blockIdx.y;
    const int tid = threadIdx.x;

    if (tid == 0) {
        int c = 0;
        #pragma unroll
        for (int i = 0; i < NPAIR; i++)
            if (eidx[i] == e) s_pair[c++] = i;
        int c4 = (c + 3) & ~3;                      // pad: duplicates of pair[0]
        for (int i = c; i < c4; i++) s_pair[i] = s_pair[0];
        s_cnt4 = (c == 0) ? 0 : c4;
    }
    __syncthreads();
    const int cnt4 = s_cnt4;
    if (cnt4 == 0) return;

    const int warp = tid >> 5;
    const int lane = tid & 31;
    const int row0 = blockIdx.x * 32 + warp * 4;

    const float4* up4 = reinterpret_cast<const float4*>(up + (size_t)e * HID * INTER);
    float4* s_h4 = reinterpret_cast<float4*>(s_h);

    for (int base = 0; base < cnt4; base += CH) {
        const int nb = (cnt4 - base < CH) ? (cnt4 - base) : CH;  // multiple of 4

        // Stage nb h-rows into smem (coalesced 256-thread copy from L2).
        __syncthreads();                            // previous super-chunk done
        for (int i = tid; i < nb * I4; i += 256) {
            const int pr = i / I4;
            const int k  = i - pr * I4;
            s_h4[i] = reinterpret_cast<const float4*>(
                g_h + (size_t)s_pair[base + pr] * INTER)[k];
        }
        __syncthreads();

        for (int rr = 0; rr < 4; rr++) {
            const int row = row0 + rr;
            const float4* ur = up4 + (size_t)row * I4;

            for (int g = 0; g < nb; g += 4) {       // groups of 4 pairs
                const float4* h0 = s_h4 + (size_t)(g + 0) * I4;
                const float4* h1 = s_h4 + (size_t)(g + 1) * I4;
                const float4* h2 = s_h4 + (size_t)(g + 2) * I4;
                const float4* h3 = s_h4 + (size_t)(g + 3) * I4;

                float a0 = 0.f, a1 = 0.f, a2 = 0.f, a3 = 0.f;

                // R10's proven inner loop: inline weight loads, 4 chains.
                #pragma unroll
                for (int j = 0; j < 22; j++) {
                    const int k = lane + 32 * j;
                    const float4 u = ur[k];         // g>0: immediate L1 hit
                    a0 = dot4(u, h0[k], a0);
                    a1 = dot4(u, h1[k], a1);
                    a2 = dot4(u, h2[k], a2);
                    a3 = dot4(u, h3[k], a3);
                }

                #pragma unroll
                for (int off = 16; off; off >>= 1) {
                    a0 += __shfl_xor_sync(0xFFFFFFFFu, a0, off);
                    a1 += __shfl_xor_sync(0xFFFFFFFFu, a1, off);
                    a2 += __shfl_xor_sync(0xFFFFFFFFu, a2, off);
                    a3 += __shfl_xor_sync(0xFFFFFFFFu, a3, off);
                }
                if (lane == 0) {
                    const int b = base + g;
                    out[(size_t)s_pair[b + 0] * HID + row] = a0;  // pads: same value
                    out[(size_t)s_pair[b + 1] * HID + row] = a1;
                    out[(size_t)s_pair[b + 2] * HID + row] = a2;
                    out[(size_t)s_pair[b + 3] * HID + row] = a3;
                }
            }
        }
    }
}

// ---------------------------------------------------------------------------
extern "C" void kernel_launch(void* const* d_in, const int* in_sizes, int n_in,
                              void* d_out, int out_size)
{
    const float* x    = (const float*)d_in[0];
    const int*   eidx = (const int*)  d_in[1];
    const float* gate = (const float*)d_in[2];
    const float* up   = (const float*)d_in[3];
    const float* down = (const float*)d_in[4];
    float* out = (float*)d_out;

    dim3 g1(INTER / 32, NEXP);   // 88 x 8
    moe_phase1<<<g1, 256>>>(x, eidx, gate, down);

    const int smem2 = CH * INTER * (int)sizeof(float);   // 90112 B
    static int attr_done = 0;    // idempotent host-side attribute set (no alloc)
    if (!attr_done) {
        cudaFuncSetAttribute(moe_phase2,
                             cudaFuncAttributeMaxDynamicSharedMemorySize, smem2);
        attr_done = 1;
    }
    dim3 g2(HID / 32, NEXP);     // 32 x 8 = 256 blocks, single wave
    moe_phase2<<<g2, 256, smem2>>>(eidx, up, out);
}